// round 15
// baseline (speedup 1.0000x reference)
#include <cuda_runtime.h>
#include <cstdint>

#define IN_DIM   256
#define OUT_DIM  256
#define N_KNOTS  9
#define NB       5
#define RPAD     16              // padded physical row slots in basis smem
#define THREADS  160             // 4 consumer warps + 1 producer warp
#define CW       (OUT_DIM * NB)  // 1280 coeff words per i-row

#define NCTA     296             // 148 SMs x 2 slots, exactly one wave
#define NBIG     248             // 248 CTAs x 14 rows + 48 x 13 = 4096

#define STAGES        3
#define STAGE_WORDS   (2 * CW)                // 2560 (2 i-rows per stage)
#define NPAIR         (IN_DIM / 2)            // 128

#define MBAR_WORDS 16
#define RING_OFF   MBAR_WORDS
#define RING_WORDS (STAGES * STAGE_WORDS)      // 7680
#define BASIS_OFF  (RING_OFF + RING_WORDS)
#define SB_WORDS   (IN_DIM * NB * RPAD)        // 20480
#define SMEM_WORDS (BASIS_OFF + SB_WORDS)
#define SMEM_BYTES (SMEM_WORDS * 4)            // 112,704 B -> 2 CTAs/SM

// ---- mbarrier PTX helpers -------------------------------------------------
#define MBAR_INIT(addr, cnt) \
    asm volatile("mbarrier.init.shared.b64 [%0], %1;" :: "r"(addr), "r"(cnt) : "memory")
#define MBAR_ARRIVE(addr) \
    asm volatile("mbarrier.arrive.shared.b64 _, [%0];" :: "r"(addr) : "memory")
#define MBAR_WAIT(addr, parity) do {                                           \
    asm volatile(                                                              \
        "{\n\t.reg .pred P;\n\t"                                              \
        "WL_%=:\n\t"                                                          \
        "mbarrier.try_wait.parity.acquire.cta.shared::cta.b64 P, [%0], %1, 0x989680;\n\t" \
        "@P bra.uni WD_%=;\n\t"                                               \
        "bra.uni WL_%=;\n\t"                                                  \
        "WD_%=:\n\t}"                                                         \
        :: "r"(addr), "r"(parity) : "memory");                                \
} while (0)

__device__ __forceinline__ uint32_t smem_u32(const void* p) {
    uint32_t a;
    asm("{ .reg .u64 t; cvta.to.shared.u64 t, %1; cvt.u32.u64 %0, t; }"
        : "=r"(a) : "l"(p));
    return a;
}

// ---- compile-time row maps --------------------------------------------------
// NR=14: logical rows 0..13 -> phys slots 0..10,12..14 (skip 11,15)
// NR=13: logical rows 0..12 -> phys slots 0..6,8..10,12..14 (skip 7,11,15)
template<int NR> __device__ __host__ constexpr int phys_of(int r) {
    return NR == 14 ? r + (r >= 11 ? 1 : 0)
                    : r + (r >= 7 ? 1 : 0) + (r >= 10 ? 1 : 0);
}
template<int NR> __device__ __host__ constexpr bool slot_ok(int s) {
    return NR == 14 ? (s != 11 && s != 15)
                    : (s != 7 && s != 11 && s != 15);
}
template<int NR> __device__ __host__ constexpr int log_of(int s) {
    return NR == 14 ? (s < 11 ? s : s - 1)
                    : (s - (s >= 8 ? 1 : 0) - (s >= 12 ? 1 : 0));
}

// ---- consumer: thread = 4 cols x phys slots [R0, R0+8), static row map ------
template<int NR, int R0>
__device__ __forceinline__ void consumer(uint32_t mb, const float* ring,
                                         const float* sbasis,
                                         float* y, float* acts,
                                         int b0, int o4, int t)
{
    float4 acc[8];
    #pragma unroll
    for (int r = 0; r < 8; r++) acc[r] = make_float4(0.f, 0.f, 0.f, 0.f);

    float* actp = acts + (size_t)b0 * (IN_DIM * OUT_DIM) + o4;

    int s = 0, ph = 0;
    for (int p = 0; p < NPAIR; p++) {
        MBAR_WAIT(mb + s * 16, ph);           // wait stage full (acquire)

        #pragma unroll
        for (int sub = 0; sub < 2; sub++) {
            const int i = 2 * p + sub;

            // coeff: 20 consecutive words at o4*5 -> 5 conflict-free LDS.128
            float4 q[5];
            const float4* cb = reinterpret_cast<const float4*>(
                &ring[s * STAGE_WORDS + sub * CW + o4 * NB]);
            #pragma unroll
            for (int j = 0; j < 5; j++) q[j] = cb[j];
            const float* f = reinterpret_cast<const float*>(q);  // f[o*5+n]

            #pragma unroll
            for (int half = 0; half < 2; half++) {
                // basis: aligned broadcast LDS.128 (4 phys slots per n)
                float4 bs[NB];
                #pragma unroll
                for (int n = 0; n < NB; n++)
                    bs[n] = *reinterpret_cast<const float4*>(
                        &sbasis[(i * NB + n) * RPAD + R0 + half * 4]);

                #pragma unroll
                for (int r = 0; r < 4; r++) {
                    const int slot = R0 + half * 4 + r;     // unroll-constant
                    if (slot_ok<NR>(slot)) {                // folds statically
                        const float bb0 = reinterpret_cast<const float*>(&bs[0])[r];
                        const float bb1 = reinterpret_cast<const float*>(&bs[1])[r];
                        const float bb2 = reinterpret_cast<const float*>(&bs[2])[r];
                        const float bb3 = reinterpret_cast<const float*>(&bs[3])[r];
                        const float bb4 = reinterpret_cast<const float*>(&bs[4])[r];
                        float4 v;
                        v.x = bb0*f[ 0] + bb1*f[ 1] + bb2*f[ 2] + bb3*f[ 3] + bb4*f[ 4];
                        v.y = bb0*f[ 5] + bb1*f[ 6] + bb2*f[ 7] + bb3*f[ 8] + bb4*f[ 9];
                        v.z = bb0*f[10] + bb1*f[11] + bb2*f[12] + bb3*f[13] + bb4*f[14];
                        v.w = bb0*f[15] + bb1*f[16] + bb2*f[17] + bb3*f[18] + bb4*f[19];

                        // plain write-back store (policy experiment vs __stcs)
                        *reinterpret_cast<float4*>(
                            actp + (size_t)log_of<NR>(slot) * (IN_DIM * OUT_DIM)
                                 + i * OUT_DIM) = v;

                        acc[slot - R0].x += v.x; acc[slot - R0].y += v.y;
                        acc[slot - R0].z += v.z; acc[slot - R0].w += v.w;
                    }
                }
            }
        }

        __syncwarp();
        if ((t & 31) == 0) MBAR_ARRIVE(mb + s * 16 + 8);    // release stage
        if (++s == STAGES) { s = 0; ph ^= 1; }
    }

    float* yp = y + (size_t)b0 * OUT_DIM + o4;
    #pragma unroll
    for (int slot = R0; slot < R0 + 8; slot++)
        if (slot_ok<NR>(slot))
            *reinterpret_cast<float4*>(
                yp + (size_t)log_of<NR>(slot) * OUT_DIM) = acc[slot - R0];
}

// ---- per-CTA body -----------------------------------------------------------
template<int NR>
__device__ __forceinline__ void body(const float* __restrict__ x,
                                     const float* __restrict__ grids,
                                     const float* __restrict__ coef,
                                     float* __restrict__ y,
                                     float* __restrict__ acts,
                                     float* smem, int b0)
{
    float* ring   = smem + RING_OFF;
    float* sbasis = smem + BASIS_OFF;
    const uint32_t mb = smem_u32(smem);   // full[s]=mb+s*16, empty[s]=mb+s*16+8

    const int t   = threadIdx.x;
    const int wid = t >> 5;

    if (t == 0) {
        #pragma unroll
        for (int s = 0; s < STAGES; s++) {
            MBAR_INIT(mb + s * 16,     32);  // full: 32 producer lanes
            MBAR_INIT(mb + s * 16 + 8,  4);  // empty: 4 elected consumer lanes
        }
    }

    // ------- Phase 1: basis. 128 consumer threads x 2 i-values x NR rows ------
    if (t < 128) {
        #pragma unroll
        for (int half = 0; half < 2; half++) {
            const int i = t + 128 * half;
            float tk[N_KNOTS];
            #pragma unroll
            for (int k = 0; k < N_KNOTS; k++) tk[k] = grids[i * N_KNOTS + k];

            float iL1[7], iR1[7], iL2[6], iR2[6], iL3[5], iR3[5];
            #pragma unroll
            for (int j = 0; j < 7; j++) { iL1[j] = 1.f / (tk[j+1] - tk[j]); iR1[j] = 1.f / (tk[j+2] - tk[j+1]); }
            #pragma unroll
            for (int j = 0; j < 6; j++) { iL2[j] = 1.f / (tk[j+2] - tk[j]); iR2[j] = 1.f / (tk[j+3] - tk[j+1]); }
            #pragma unroll
            for (int j = 0; j < 5; j++) { iL3[j] = 1.f / (tk[j+3] - tk[j]); iR3[j] = 1.f / (tk[j+4] - tk[j+1]); }

            const int rot = i % NR;
            #pragma unroll
            for (int rr = 0; rr < NR; rr++) {
                int r = rr + rot; if (r >= NR) r -= NR;    // bank-spreading rotation
                const float xv = x[(size_t)(b0 + r) * IN_DIM + i];
                float bas[8];
                #pragma unroll
                for (int j = 0; j < 8; j++)
                    bas[j] = (xv >= tk[j] && xv < tk[j+1]) ? 1.0f : 0.0f;
                #pragma unroll
                for (int j = 0; j < 7; j++)
                    bas[j] = (xv - tk[j]) * iL1[j] * bas[j] + (tk[j+2] - xv) * iR1[j] * bas[j+1];
                #pragma unroll
                for (int j = 0; j < 6; j++)
                    bas[j] = (xv - tk[j]) * iL2[j] * bas[j] + (tk[j+3] - xv) * iR2[j] * bas[j+1];
                #pragma unroll
                for (int j = 0; j < 5; j++)
                    bas[j] = (xv - tk[j]) * iL3[j] * bas[j] + (tk[j+4] - xv) * iR3[j] * bas[j+1];

                const int phys = phys_of<NR>(r);
                #pragma unroll
                for (int n = 0; n < NB; n++)
                    sbasis[(i * NB + n) * RPAD + phys] = bas[n];
            }
        }
    }
    __syncthreads();   // publishes basis + mbarrier init; the ONLY block barrier

    if (wid == 4) {
        // ---------------- Producer warp: stream coeff rows through the ring ---
        const int lane = t & 31;
        int s = 0, ph = 1;                      // fresh empties pass parity 1
        for (int p = 0; p < NPAIR; p++) {
            MBAR_WAIT(mb + s * 16 + 8, ph);     // wait stage empty
            const float4* src = reinterpret_cast<const float4*>(
                coef + (size_t)(2 * p) * CW);
            float4* dst = reinterpret_cast<float4*>(ring + s * STAGE_WORDS);
            float4 v[20];
            #pragma unroll
            for (int k = 0; k < 20; k++) v[k] = src[lane + 32 * k];
            #pragma unroll
            for (int k = 0; k < 20; k++) dst[lane + 32 * k] = v[k];
            MBAR_ARRIVE(mb + s * 16);           // all 32 lanes -> full
            if (++s == STAGES) { s = 0; ph ^= 1; }
        }
    } else {
        const int o4 = (t & 63) * 4;
        if ((t >> 6) == 0) consumer<NR, 0>(mb, ring, sbasis, y, acts, b0, o4, t);
        else               consumer<NR, 8>(mb, ring, sbasis, y, acts, b0, o4, t);
    }
}

__global__ __launch_bounds__(THREADS, 2)
void kan_kernel(const float* __restrict__ x,
                const float* __restrict__ grids,
                const float* __restrict__ coef,
                float* __restrict__ y,
                float* __restrict__ acts)
{
    extern __shared__ float smem[];
    const int c = blockIdx.x;

    if (c < NBIG) body<14>(x, grids, coef, y, acts, smem, c * 14);
    else          body<13>(x, grids, coef, y, acts, smem,
                           NBIG * 14 + (c - NBIG) * 13);
}

extern "C" void kernel_launch(void* const* d_in, const int* in_sizes, int n_in,
                              void* d_out, int out_size)
{
    const float* x     = (const float*)d_in[0];
    const float* grids = (const float*)d_in[1];
    const float* coef  = (const float*)d_in[2];

    const int B = in_sizes[0] / IN_DIM;   // 4096

    float* y    = (float*)d_out;
    float* acts = (float*)d_out + (size_t)B * OUT_DIM;

    cudaFuncSetAttribute(kan_kernel,
                         cudaFuncAttributeMaxDynamicSharedMemorySize, SMEM_BYTES);
    kan_kernel<<<NCTA, THREADS, SMEM_BYTES>>>(x, grids, coef, y, acts);
}

// round 16
// speedup vs baseline: 1.3210x; 1.3210x over previous
#include <cuda_runtime.h>
#include <cstdint>

#define IN_DIM   256
#define OUT_DIM  256
#define N_KNOTS  9
#define NB       5
#define RPAD     16              // padded physical row slots in basis smem
#define THREADS  160             // 4 consumer warps + 1 producer warp
#define CW       (OUT_DIM * NB)  // 1280 coeff words per i-row

#define NCTA     296             // 148 SMs x 2 slots, exactly one wave
#define NBIG     248             // 248 CTAs x 14 rows + 48 x 13 = 4096

#define STAGES        3
#define STAGE_WORDS   (2 * CW)                // 2560 (2 i-rows per stage)
#define NPAIR         (IN_DIM / 2)            // 128

#define MBAR_WORDS 16
#define RING_OFF   MBAR_WORDS
#define RING_WORDS (STAGES * STAGE_WORDS)      // 7680
#define BASIS_OFF  (RING_OFF + RING_WORDS)
#define SB_WORDS   (IN_DIM * NB * RPAD)        // 20480
#define SMEM_WORDS (BASIS_OFF + SB_WORDS)
#define SMEM_BYTES (SMEM_WORDS * 4)            // 112,704 B -> 2 CTAs/SM

// ---- mbarrier PTX helpers -------------------------------------------------
#define MBAR_INIT(addr, cnt) \
    asm volatile("mbarrier.init.shared.b64 [%0], %1;" :: "r"(addr), "r"(cnt) : "memory")
#define MBAR_ARRIVE(addr) \
    asm volatile("mbarrier.arrive.shared.b64 _, [%0];" :: "r"(addr) : "memory")
#define MBAR_WAIT(addr, parity) do {                                           \
    asm volatile(                                                              \
        "{\n\t.reg .pred P;\n\t"                                              \
        "WL_%=:\n\t"                                                          \
        "mbarrier.try_wait.parity.acquire.cta.shared::cta.b64 P, [%0], %1, 0x989680;\n\t" \
        "@P bra.uni WD_%=;\n\t"                                               \
        "bra.uni WL_%=;\n\t"                                                  \
        "WD_%=:\n\t}"                                                         \
        :: "r"(addr), "r"(parity) : "memory");                                \
} while (0)

__device__ __forceinline__ uint32_t smem_u32(const void* p) {
    uint32_t a;
    asm("{ .reg .u64 t; cvta.to.shared.u64 t, %1; cvt.u32.u64 %0, t; }"
        : "=r"(a) : "l"(p));
    return a;
}

// ---- compile-time row maps --------------------------------------------------
// NR=14: logical rows 0..13 -> phys slots 0..10,12..14 (skip 11,15)
// NR=13: logical rows 0..12 -> phys slots 0..6,8..10,12..14 (skip 7,11,15)
template<int NR> __device__ __host__ constexpr int phys_of(int r) {
    return NR == 14 ? r + (r >= 11 ? 1 : 0)
                    : r + (r >= 7 ? 1 : 0) + (r >= 10 ? 1 : 0);
}
template<int NR> __device__ __host__ constexpr bool slot_ok(int s) {
    return NR == 14 ? (s != 11 && s != 15)
                    : (s != 7 && s != 11 && s != 15);
}
template<int NR> __device__ __host__ constexpr int log_of(int s) {
    return NR == 14 ? (s < 11 ? s : s - 1)
                    : (s - (s >= 8 ? 1 : 0) - (s >= 12 ? 1 : 0));
}

// ---- consumer: thread = 4 cols x phys slots [R0, R0+8), static row map ------
template<int NR, int R0>
__device__ __forceinline__ void consumer(uint32_t mb, const float* ring,
                                         const float* sbasis,
                                         float* y, float* acts,
                                         int b0, int o4, int t)
{
    float4 acc[8];
    #pragma unroll
    for (int r = 0; r < 8; r++) acc[r] = make_float4(0.f, 0.f, 0.f, 0.f);

    float* actp = acts + (size_t)b0 * (IN_DIM * OUT_DIM) + o4;

    int s = 0, ph = 0;
    for (int p = 0; p < NPAIR; p++) {
        MBAR_WAIT(mb + s * 16, ph);           // wait stage full (acquire)

        #pragma unroll
        for (int sub = 0; sub < 2; sub++) {
            const int i = 2 * p + sub;

            // coeff: 20 consecutive words at o4*5 -> 5 conflict-free LDS.128
            float4 q[5];
            const float4* cb = reinterpret_cast<const float4*>(
                &ring[s * STAGE_WORDS + sub * CW + o4 * NB]);
            #pragma unroll
            for (int j = 0; j < 5; j++) q[j] = cb[j];
            const float* f = reinterpret_cast<const float*>(q);  // f[o*5+n]

            #pragma unroll
            for (int half = 0; half < 2; half++) {
                // basis: aligned broadcast LDS.128 (4 phys slots per n)
                float4 bs[NB];
                #pragma unroll
                for (int n = 0; n < NB; n++)
                    bs[n] = *reinterpret_cast<const float4*>(
                        &sbasis[(i * NB + n) * RPAD + R0 + half * 4]);

                #pragma unroll
                for (int r = 0; r < 4; r++) {
                    const int slot = R0 + half * 4 + r;     // unroll-constant
                    if (slot_ok<NR>(slot)) {                // folds statically
                        const float bb0 = reinterpret_cast<const float*>(&bs[0])[r];
                        const float bb1 = reinterpret_cast<const float*>(&bs[1])[r];
                        const float bb2 = reinterpret_cast<const float*>(&bs[2])[r];
                        const float bb3 = reinterpret_cast<const float*>(&bs[3])[r];
                        const float bb4 = reinterpret_cast<const float*>(&bs[4])[r];
                        float4 v;
                        v.x = bb0*f[ 0] + bb1*f[ 1] + bb2*f[ 2] + bb3*f[ 3] + bb4*f[ 4];
                        v.y = bb0*f[ 5] + bb1*f[ 6] + bb2*f[ 7] + bb3*f[ 8] + bb4*f[ 9];
                        v.z = bb0*f[10] + bb1*f[11] + bb2*f[12] + bb3*f[13] + bb4*f[14];
                        v.w = bb0*f[15] + bb1*f[16] + bb2*f[17] + bb3*f[18] + bb4*f[19];

                        // streaming store: acts is write-once, never re-read.
                        // R15 proved .cs is worth ~23% (evict-first keeps the
                        // coeff working set resident in L2).
                        __stcs(reinterpret_cast<float4*>(
                            actp + (size_t)log_of<NR>(slot) * (IN_DIM * OUT_DIM)
                                 + i * OUT_DIM), v);

                        acc[slot - R0].x += v.x; acc[slot - R0].y += v.y;
                        acc[slot - R0].z += v.z; acc[slot - R0].w += v.w;
                    }
                }
            }
        }

        __syncwarp();
        if ((t & 31) == 0) MBAR_ARRIVE(mb + s * 16 + 8);    // release stage
        if (++s == STAGES) { s = 0; ph ^= 1; }
    }

    float* yp = y + (size_t)b0 * OUT_DIM + o4;
    #pragma unroll
    for (int slot = R0; slot < R0 + 8; slot++)
        if (slot_ok<NR>(slot))
            *reinterpret_cast<float4*>(
                yp + (size_t)log_of<NR>(slot) * OUT_DIM) = acc[slot - R0];
}

// ---- per-CTA body -----------------------------------------------------------
template<int NR>
__device__ __forceinline__ void body(const float* __restrict__ x,
                                     const float* __restrict__ grids,
                                     const float* __restrict__ coef,
                                     float* __restrict__ y,
                                     float* __restrict__ acts,
                                     float* smem, int b0)
{
    float* ring   = smem + RING_OFF;
    float* sbasis = smem + BASIS_OFF;
    const uint32_t mb = smem_u32(smem);   // full[s]=mb+s*16, empty[s]=mb+s*16+8

    const int t   = threadIdx.x;
    const int wid = t >> 5;

    if (t == 0) {
        #pragma unroll
        for (int s = 0; s < STAGES; s++) {
            MBAR_INIT(mb + s * 16,     32);  // full: 32 producer lanes
            MBAR_INIT(mb + s * 16 + 8,  4);  // empty: 4 elected consumer lanes
        }
    }

    // ------- Phase 1: basis. 128 consumer threads x 2 i-values x NR rows ------
    if (t < 128) {
        #pragma unroll
        for (int half = 0; half < 2; half++) {
            const int i = t + 128 * half;
            float tk[N_KNOTS];
            #pragma unroll
            for (int k = 0; k < N_KNOTS; k++) tk[k] = grids[i * N_KNOTS + k];

            float iL1[7], iR1[7], iL2[6], iR2[6], iL3[5], iR3[5];
            #pragma unroll
            for (int j = 0; j < 7; j++) { iL1[j] = 1.f / (tk[j+1] - tk[j]); iR1[j] = 1.f / (tk[j+2] - tk[j+1]); }
            #pragma unroll
            for (int j = 0; j < 6; j++) { iL2[j] = 1.f / (tk[j+2] - tk[j]); iR2[j] = 1.f / (tk[j+3] - tk[j+1]); }
            #pragma unroll
            for (int j = 0; j < 5; j++) { iL3[j] = 1.f / (tk[j+3] - tk[j]); iR3[j] = 1.f / (tk[j+4] - tk[j+1]); }

            const int rot = i % NR;
            #pragma unroll
            for (int rr = 0; rr < NR; rr++) {
                int r = rr + rot; if (r >= NR) r -= NR;    // bank-spreading rotation
                const float xv = x[(size_t)(b0 + r) * IN_DIM + i];
                float bas[8];
                #pragma unroll
                for (int j = 0; j < 8; j++)
                    bas[j] = (xv >= tk[j] && xv < tk[j+1]) ? 1.0f : 0.0f;
                #pragma unroll
                for (int j = 0; j < 7; j++)
                    bas[j] = (xv - tk[j]) * iL1[j] * bas[j] + (tk[j+2] - xv) * iR1[j] * bas[j+1];
                #pragma unroll
                for (int j = 0; j < 6; j++)
                    bas[j] = (xv - tk[j]) * iL2[j] * bas[j] + (tk[j+3] - xv) * iR2[j] * bas[j+1];
                #pragma unroll
                for (int j = 0; j < 5; j++)
                    bas[j] = (xv - tk[j]) * iL3[j] * bas[j] + (tk[j+4] - xv) * iR3[j] * bas[j+1];

                const int phys = phys_of<NR>(r);
                #pragma unroll
                for (int n = 0; n < NB; n++)
                    sbasis[(i * NB + n) * RPAD + phys] = bas[n];
            }
        }
    }
    __syncthreads();   // publishes basis + mbarrier init; the ONLY block barrier

    if (wid == 4) {
        // ---------------- Producer warp: stream coeff rows through the ring ---
        const int lane = t & 31;
        int s = 0, ph = 1;                      // fresh empties pass parity 1
        for (int p = 0; p < NPAIR; p++) {
            MBAR_WAIT(mb + s * 16 + 8, ph);     // wait stage empty
            const float4* src = reinterpret_cast<const float4*>(
                coef + (size_t)(2 * p) * CW);
            float4* dst = reinterpret_cast<float4*>(ring + s * STAGE_WORDS);
            float4 v[20];
            #pragma unroll
            for (int k = 0; k < 20; k++) v[k] = src[lane + 32 * k];
            #pragma unroll
            for (int k = 0; k < 20; k++) dst[lane + 32 * k] = v[k];
            MBAR_ARRIVE(mb + s * 16);           // all 32 lanes -> full
            if (++s == STAGES) { s = 0; ph ^= 1; }
        }
    } else {
        const int o4 = (t & 63) * 4;
        if ((t >> 6) == 0) consumer<NR, 0>(mb, ring, sbasis, y, acts, b0, o4, t);
        else               consumer<NR, 8>(mb, ring, sbasis, y, acts, b0, o4, t);
    }
}

__global__ __launch_bounds__(THREADS, 2)
void kan_kernel(const float* __restrict__ x,
                const float* __restrict__ grids,
                const float* __restrict__ coef,
                float* __restrict__ y,
                float* __restrict__ acts)
{
    extern __shared__ float smem[];
    const int c = blockIdx.x;

    if (c < NBIG) body<14>(x, grids, coef, y, acts, smem, c * 14);
    else          body<13>(x, grids, coef, y, acts, smem,
                           NBIG * 14 + (c - NBIG) * 13);
}

extern "C" void kernel_launch(void* const* d_in, const int* in_sizes, int n_in,
                              void* d_out, int out_size)
{
    const float* x     = (const float*)d_in[0];
    const float* grids = (const float*)d_in[1];
    const float* coef  = (const float*)d_in[2];

    const int B = in_sizes[0] / IN_DIM;   // 4096

    float* y    = (float*)d_out;
    float* acts = (float*)d_out + (size_t)B * OUT_DIM;

    cudaFuncSetAttribute(kan_kernel,
                         cudaFuncAttributeMaxDynamicSharedMemorySize, SMEM_BYTES);
    kan_kernel<<<NCTA, THREADS, SMEM_BYTES>>>(x, grids, coef, y, acts);
}